// round 3
// baseline (speedup 1.0000x reference)
#include <cuda_runtime.h>
#include <cuda_bf16.h>
#include <math.h>
#include <stdint.h>

#define N_NODES 65536
#define N_EDGES 524288
#define HIDDEN 128
#define OUTDIM 10
#define NUM_GRAPHS 64
#define SLOT_CAP 64

// ---------------- scratch (device globals; no allocation allowed) ----------
__device__ __align__(16) static float g_agg[(size_t)N_NODES * HIDDEN];
__device__ __align__(16) static float g_h[(size_t)N_NODES * HIDDEN];
__device__ static int   g_deg[N_NODES];
__device__ static int   g_slots[(size_t)N_NODES * SLOT_CAP];
__device__ static float g_gsum[NUM_GRAPHS * HIDDEN];
__device__ static float g_gcnt[NUM_GRAPHS];
__device__ static int   g_is64;

// ---------------- index dtype detection ------------------------------------
__global__ void detect_kernel(const unsigned int* __restrict__ w) {
    bool is64 = true;
    for (int i = 1; i < 256; i += 2) {
        if (w[i] != 0u) { is64 = false; break; }
    }
    g_is64 = is64 ? 1 : 0;
}

__device__ __forceinline__ int load_idx(const void* p, int i, int is64) {
    if (is64) return (int)((const long long*)p)[i];
    return ((const int*)p)[i];
}

// ---------------- zero scratch ----------------------------------------------
__global__ void zero_kernel() {
    int i = blockIdx.x * blockDim.x + threadIdx.x;
    if (i < N_NODES) g_deg[i] = 0;
    if (i < NUM_GRAPHS * HIDDEN) g_gsum[i] = 0.0f;
    if (i < NUM_GRAPHS) g_gcnt[i] = 0.0f;
}

// ---------------- bucketed inverse adjacency ---------------------------------
__global__ void build_kernel(const void* __restrict__ src,
                             const void* __restrict__ dst) {
    int e = blockIdx.x * blockDim.x + threadIdx.x;
    if (e >= N_EDGES) return;
    int is64 = g_is64;
    int d = load_idx(dst, e, is64);
    int s = load_idx(src, e, is64);
    int pos = atomicAdd(&g_deg[d], 1);
    if (pos < SLOT_CAP) g_slots[(size_t)d * SLOT_CAP + pos] = s;
}

// ---------------- per-node gather-sum -----------------------------------------
__global__ void gather_kernel(const float* __restrict__ hin,
                              float* __restrict__ agg) {
    int w = (blockIdx.x * blockDim.x + threadIdx.x) >> 5;
    int lane = threadIdx.x & 31;
    if (w >= N_NODES) return;
    int deg = g_deg[w];
    if (deg > SLOT_CAP) deg = SLOT_CAP;
    const int* slots = g_slots + (size_t)w * SLOT_CAP;
    int s0 = (lane < deg) ? slots[lane] : 0;
    int s1 = (32 + lane < deg) ? slots[32 + lane] : 0;
    float4 acc = make_float4(0.f, 0.f, 0.f, 0.f);
    for (int i = 0; i < deg; i++) {
        int s = __shfl_sync(0xffffffffu, (i < 32) ? s0 : s1, i & 31);
        float4 v = __ldg((const float4*)(hin + (size_t)s * HIDDEN) + lane);
        acc.x += v.x; acc.y += v.y; acc.z += v.z; acc.w += v.w;
    }
    ((float4*)(agg + (size_t)w * HIDDEN))[lane] = acc;
}

// ================= TF32 mma.sync GEMM (sm_80+ path; no 103a features) ========
__device__ __forceinline__ void tf32_split(float v, uint32_t& hb, uint32_t& lb) {
    asm("cvt.rna.tf32.f32 %0, %1;" : "=r"(hb) : "f"(v));
    float r = v - __uint_as_float(hb);
    asm("cvt.rna.tf32.f32 %0, %1;" : "=r"(lb) : "f"(r));
}

__device__ __forceinline__ void mma_tf32(float* c,
                                         uint32_t a0, uint32_t a1, uint32_t a2, uint32_t a3,
                                         uint32_t b0, uint32_t b1) {
    asm volatile(
        "mma.sync.aligned.m16n8k8.row.col.f32.tf32.tf32.f32 "
        "{%0,%1,%2,%3}, {%4,%5,%6,%7}, {%8,%9}, {%0,%1,%2,%3};"
        : "+f"(c[0]), "+f"(c[1]), "+f"(c[2]), "+f"(c[3])
        : "r"(a0), "r"(a1), "r"(a2), "r"(a3), "r"(b0), "r"(b1));
}

// smem strides (in 32-bit words), chosen conflict-free for the fragment patterns
#define AS_STRIDE 132
#define WS_STRIDE 136
#define SM_WH_OFF 0
#define SM_WL_OFF (128 * WS_STRIDE)
#define SM_AS_OFF (2 * 128 * WS_STRIDE)
#define GEMM_SMEM_BYTES ((2 * 128 * WS_STRIDE + 128 * AS_STRIDE) * 4)

// One CTA = 128 rows x 128 cols. 256 threads = 8 warps (2 M x 4 N), warp tile 64x32.
__global__ void __launch_bounds__(256, 1)
gemm_tc_kernel(const float* __restrict__ A, const float* __restrict__ W,
               const float* __restrict__ b, float* __restrict__ out) {
    extern __shared__ __align__(16) float smem[];
    uint32_t* Wh = (uint32_t*)(smem + SM_WH_OFF);
    uint32_t* Wl = (uint32_t*)(smem + SM_WL_OFF);
    float*    As = smem + SM_AS_OFF;

    int tid = threadIdx.x;
    int lane = tid & 31, wid = tid >> 5;
    int gq = lane >> 2, tq = lane & 3;      // quad group / thread-in-quad
    int warp_m = wid & 1, warp_n = wid >> 1;

    // ---- stage W: split to tf32 hi/lo (coalesced read, conflict-free store) ----
    for (int i = tid; i < 128 * 128; i += 256) {
        int k = i >> 7, n = i & 127;
        float w = __ldg(W + i);
        uint32_t hb, lb;
        tf32_split(w, hb, lb);
        Wh[k * WS_STRIDE + n] = hb;
        Wl[k * WS_STRIDE + n] = lb;
    }

    // ---- stage A tile (float4, coalesced) ----
    const float4* A4 = (const float4*)(A + (size_t)blockIdx.x * 128 * HIDDEN);
    for (int i = tid; i < 128 * 32; i += 256) {
        int r = i >> 5, c4 = i & 31;
        *(float4*)(As + r * AS_STRIDE + c4 * 4) = __ldg(A4 + i);
    }
    __syncthreads();

    float acc[4][4][4];
#pragma unroll
    for (int mi = 0; mi < 4; mi++)
#pragma unroll
        for (int ni = 0; ni < 4; ni++)
#pragma unroll
            for (int r = 0; r < 4; r++) acc[mi][ni][r] = 0.0f;

    const int mBase = warp_m * 64;
    const int nBase = warp_n * 32;

#pragma unroll 2
    for (int ks = 0; ks < 16; ks++) {
        int k0 = ks * 8;
        uint32_t ah[4][4], al[4][4];
#pragma unroll
        for (int mi = 0; mi < 4; mi++) {
            int r = mBase + mi * 16 + gq;
            float x0 = As[r * AS_STRIDE + k0 + tq];
            float x1 = As[(r + 8) * AS_STRIDE + k0 + tq];
            float x2 = As[r * AS_STRIDE + k0 + tq + 4];
            float x3 = As[(r + 8) * AS_STRIDE + k0 + tq + 4];
            tf32_split(x0, ah[mi][0], al[mi][0]);
            tf32_split(x1, ah[mi][1], al[mi][1]);
            tf32_split(x2, ah[mi][2], al[mi][2]);
            tf32_split(x3, ah[mi][3], al[mi][3]);
        }
        uint32_t bh[4][2], bl[4][2];
#pragma unroll
        for (int ni = 0; ni < 4; ni++) {
            int c = nBase + ni * 8 + gq;
            bh[ni][0] = Wh[(k0 + tq) * WS_STRIDE + c];
            bh[ni][1] = Wh[(k0 + tq + 4) * WS_STRIDE + c];
            bl[ni][0] = Wl[(k0 + tq) * WS_STRIDE + c];
            bl[ni][1] = Wl[(k0 + tq + 4) * WS_STRIDE + c];
        }
#pragma unroll
        for (int mi = 0; mi < 4; mi++)
#pragma unroll
            for (int ni = 0; ni < 4; ni++) {
                mma_tf32(acc[mi][ni], ah[mi][0], ah[mi][1], ah[mi][2], ah[mi][3],
                         bh[ni][0], bh[ni][1]);
                mma_tf32(acc[mi][ni], ah[mi][0], ah[mi][1], ah[mi][2], ah[mi][3],
                         bl[ni][0], bl[ni][1]);
                mma_tf32(acc[mi][ni], al[mi][0], al[mi][1], al[mi][2], al[mi][3],
                         bh[ni][0], bh[ni][1]);
            }
    }

    // ---- epilogue: bias + ELU + store ----
    size_t rowBase = (size_t)blockIdx.x * 128;
#pragma unroll
    for (int mi = 0; mi < 4; mi++) {
        int r0 = mBase + mi * 16 + gq;
#pragma unroll
        for (int ni = 0; ni < 4; ni++) {
            int c0 = nBase + ni * 8 + 2 * tq;
            float2 bb = __ldg((const float2*)(b + c0));
            float v0 = acc[mi][ni][0] + bb.x;
            float v1 = acc[mi][ni][1] + bb.y;
            float v2 = acc[mi][ni][2] + bb.x;
            float v3 = acc[mi][ni][3] + bb.y;
            v0 = v0 > 0.f ? v0 : expm1f(v0);
            v1 = v1 > 0.f ? v1 : expm1f(v1);
            v2 = v2 > 0.f ? v2 : expm1f(v2);
            v3 = v3 > 0.f ? v3 : expm1f(v3);
            float2 p0 = make_float2(v0, v1);
            float2 p1 = make_float2(v2, v3);
            *(float2*)(out + (rowBase + r0) * HIDDEN + c0) = p0;
            *(float2*)(out + (rowBase + r0 + 8) * HIDDEN + c0) = p1;
        }
    }
}

// ---------------- graph readout ----------------------------------------------
__global__ void count_kernel(const void* __restrict__ gid) {
    int i = blockIdx.x * blockDim.x + threadIdx.x;
    if (i >= N_NODES) return;
    int g = load_idx(gid, i, g_is64);
    atomicAdd(&g_gcnt[g], 1.0f);
}

__global__ void readout_kernel(const float* __restrict__ h,
                               const void* __restrict__ gid) {
    int t = threadIdx.x;
    int base = blockIdx.x * 128;
    int is64 = g_is64;
    int cur = load_idx(gid, base, is64);
    float acc = 0.0f;
    for (int n = 0; n < 128; n++) {
        int node = base + n;
        int g = load_idx(gid, node, is64);
        if (g != cur) {
            atomicAdd(&g_gsum[cur * HIDDEN + t], acc);
            acc = 0.0f; cur = g;
        }
        acc += h[(size_t)node * HIDDEN + t];
    }
    atomicAdd(&g_gsum[cur * HIDDEN + t], acc);
}

__global__ void classifier_kernel(const float* __restrict__ Wc,
                                  const float* __restrict__ bc,
                                  float* __restrict__ out) {
    int t = blockIdx.x * blockDim.x + threadIdx.x;
    if (t >= NUM_GRAPHS * OUTDIM) return;
    int g = t / OUTDIM, o = t % OUTDIM;
    float c = fmaxf(g_gcnt[g], 1.0f);
    float inv = 1.0f / c;
    float acc = bc[o];
#pragma unroll 8
    for (int k = 0; k < HIDDEN; k++)
        acc += g_gsum[g * HIDDEN + k] * inv * Wc[k * OUTDIM + o];
    out[t] = acc;
}

// ---------------- launch -------------------------------------------------------
extern "C" void kernel_launch(void* const* d_in, const int* in_sizes, int n_in,
                              void* d_out, int out_size) {
    const float* features = (const float*)d_in[0];
    const void*  src      = d_in[1];
    const void*  dst      = d_in[2];
    const void*  gids     = d_in[3];
    const float* W1 = (const float*)d_in[4];
    const float* b1 = (const float*)d_in[5];
    const float* W2 = (const float*)d_in[6];
    const float* b2 = (const float*)d_in[7];
    const float* W3 = (const float*)d_in[8];
    const float* b3 = (const float*)d_in[9];
    const float* Wc = (const float*)d_in[10];
    const float* bc = (const float*)d_in[11];
    float* out = (float*)d_out;

    float* agg; cudaGetSymbolAddress((void**)&agg, g_agg);
    float* h;   cudaGetSymbolAddress((void**)&h, g_h);

    cudaFuncSetAttribute(gemm_tc_kernel,
                         cudaFuncAttributeMaxDynamicSharedMemorySize, GEMM_SMEM_BYTES);

    detect_kernel<<<1, 1>>>((const unsigned int*)src);
    zero_kernel<<<N_NODES / 256, 256>>>();
    build_kernel<<<N_EDGES / 256, 256>>>(src, dst);

    const int GATHER_BLOCKS = (N_NODES * 32) / 256;
    const int GEMM_BLOCKS = N_NODES / 128;

    gather_kernel<<<GATHER_BLOCKS, 256>>>(features, agg);
    gemm_tc_kernel<<<GEMM_BLOCKS, 256, GEMM_SMEM_BYTES>>>(agg, W1, b1, h);
    gather_kernel<<<GATHER_BLOCKS, 256>>>(h, agg);
    gemm_tc_kernel<<<GEMM_BLOCKS, 256, GEMM_SMEM_BYTES>>>(agg, W2, b2, h);
    gather_kernel<<<GATHER_BLOCKS, 256>>>(h, agg);
    gemm_tc_kernel<<<GEMM_BLOCKS, 256, GEMM_SMEM_BYTES>>>(agg, W3, b3, h);

    count_kernel<<<N_NODES / 256, 256>>>(gids);
    readout_kernel<<<N_NODES / 128, 128>>>(h, gids);
    classifier_kernel<<<1, NUM_GRAPHS * OUTDIM>>>(Wc, bc, out);
}